// round 16
// baseline (speedup 1.0000x reference)
#include <cuda_runtime.h>
#include <cuda_bf16.h>
#include <math.h>

// Problem constants
#define B_  16
#define T_  12
#define N_  325
#define D_  64
#define L_  2
#define G_  192
#define BN  (B_ * N_)          // 5200

// d_out layout (floats): output, hidden, attn_input, attn_hidden
#define SZ_OUT ((size_t)B_ * T_ * N_ * D_)
#define SZ_HID ((size_t)B_ * L_ * N_ * D_)
#define SZ_A   ((size_t)B_ * T_ * L_ * N_ * N_)
#define OFF_OUT 0
#define OFF_HID (SZ_OUT)
#define OFF_AI  (SZ_OUT + SZ_HID)
#define OFF_AH  (SZ_OUT + SZ_HID + SZ_A)

// Scratch, parity double-buffered (stage s reads [s&1], gate writes [(s+1)&1])
__device__ float g_Xbuf[2][BN * D_];
__device__ float g_Qbuf[2][2][BN * D_];   // [parity][gat]
__device__ float g_Kbuf[2][2][BN * D_];
__device__ float g_O[2][BN * G_];
__device__ unsigned g_flag[24 * 16 * 9];  // per (stage, b, rt); zeroed each run

typedef unsigned long long ull;

__device__ __forceinline__ void ffma2(ull& d, ull a, ull b) {
    asm volatile("fma.rn.f32x2 %0, %1, %2, %0;" : "+l"(d) : "l"(a), "l"(b));
}
__device__ __forceinline__ float f2sum(ull v) {
    float lo, hi;
    asm("mov.b64 {%0, %1}, %2;" : "=f"(lo), "=f"(hi) : "l"(v));
    return lo + hi;
}
// FMA-pipe exp (x <= 0 here), ~1e-7 rel err.
__device__ __forceinline__ float fexp(float x) {
    float t = fmaxf(x * 1.4426950408889634f, -126.0f);
    float fi = floorf(t);
    float f = t - fi;
    float p =             1.535336188319500e-4f;
    p = fmaf(p, f, 1.339887440266574e-3f);
    p = fmaf(p, f, 9.618437357674640e-3f);
    p = fmaf(p, f, 5.550332471162809e-2f);
    p = fmaf(p, f, 2.402264791363012e-1f);
    p = fmaf(p, f, 6.931472028550421e-1f);
    p = fmaf(p, f, 1.0f);
    return p * __int_as_float(((int)fi + 127) << 23);
}

// ---------------------------------------------------------------------------
__global__ void init_kernel(float* __restrict__ outf) {
    size_t i = (size_t)blockIdx.x * blockDim.x + threadIdx.x;
    if (i < SZ_HID) outf[OFF_HID + i] = 0.0f;
    if (i < 24 * 16 * 9) g_flag[i] = 0u;
}

// ---------------------------------------------------------------------------
// Prologue: Q/K for stage (t=0,l=0) from x[:,0] -> parity 0. grid (82,4), 256.
// ---------------------------------------------------------------------------
__global__ void qk_prologue(const float* __restrict__ x,
                            const float* __restrict__ Wq_i, const float* __restrict__ Wk_i,
                            const float* __restrict__ Wq_h, const float* __restrict__ Wk_h) {
    __shared__ float Xs[64 * 68];
    __shared__ float Wt[64 * 66];
    const int rb = blockIdx.x, cb = blockIdx.y, tid = threadIdx.x;

    for (int idx = tid; idx < 64 * 64; idx += 256) {
        int r = idx >> 6, k = idx & 63;
        int row = rb * 64 + r;
        float v = 0.0f;
        if (row < BN) {
            int bb = row / N_, n = row - bb * N_;
            v = x[(((size_t)bb * T_) * N_ + n) * D_ + k];
        }
        Xs[r * 68 + k] = v;
    }
    const int g = cb >> 1, isK = cb & 1;
    const float* W = (g ? (isK ? Wk_h : Wq_h) : (isK ? Wk_i : Wq_i));
    for (int idx = tid; idx < 64 * 64; idx += 256) {
        int k = idx >> 6, c = idx & 63;
        Wt[c * 66 + k] = W[k * 64 + c];
    }
    __syncthreads();

    const int ty = tid >> 4, tx = tid & 15;
    ull acc[4][4] = {};
#pragma unroll
    for (int k = 0; k < 64; k += 4) {
        ulonglong2 xv[4];
#pragma unroll
        for (int m = 0; m < 4; m++)
            xv[m] = *(const ulonglong2*)&Xs[(ty + 16 * m) * 68 + k];
#pragma unroll
        for (int j = 0; j < 4; j++) {
            const int c = tx + 16 * j;
            ull w0 = *(const ull*)&Wt[c * 66 + k];
            ull w1 = *(const ull*)&Wt[c * 66 + k + 2];
#pragma unroll
            for (int m = 0; m < 4; m++) {
                ffma2(acc[m][j], xv[m].x, w0);
                ffma2(acc[m][j], xv[m].y, w1);
            }
        }
    }
    float* dst = isK ? g_Kbuf[0][g] : g_Qbuf[0][g];
#pragma unroll
    for (int m = 0; m < 4; m++) {
        int row = rb * 64 + ty + 16 * m;
        if (row < BN) {
#pragma unroll
            for (int j = 0; j < 4; j++)
                dst[(size_t)row * 64 + tx + 16 * j] = f2sum(acc[m][j]);
        }
    }
}

// ---------------------------------------------------------------------------
// Stage kernel: attention per (tile, gat, batch) + last-arriver gate tail.
// grid (9, 2, 16)=288, block 256, smem 106 KB -> 2 CTAs/SM, single wave.
// Warp w owns rows w+8m (m<5) in attention phases.
// ---------------------------------------------------------------------------
#define RT     40
#define NTILES 9
#define NPADS  384
#define QSTR   68
#define KSTR   66
#define CH_ONE (64 * KSTR)                  // 4224
#define SM_S   (RT * QSTR)                  // 2720
#define SM_CH  (SM_S + RT * NPADS)          // 18080
#define K1_SMEM_FLOATS (SM_CH + 2 * CH_ONE) // 26528 -> 106,112 B

__global__ __launch_bounds__(256, 2)
void attn_gate_kernel(int s, int t, int l, int from_x, int do_qk, int l_next, int par,
                      const float* __restrict__ x,
                      const float* __restrict__ Wq_i, const float* __restrict__ Wk_i,
                      const float* __restrict__ Wv_i, const float* __restrict__ b_i,
                      const float* __restrict__ Wq_h, const float* __restrict__ Wk_h,
                      const float* __restrict__ Wv_h, const float* __restrict__ b_h,
                      const float* __restrict__ ln_g, const float* __restrict__ ln_b,
                      float* __restrict__ outf) {
    extern __shared__ float sm[];
    float* Qs = sm;               // Q tile -> PX -> y tile (gate)
    float* S  = sm + SM_S;        // scores/P -> Wt
    float* CH = sm + SM_CH;       // 2 x (64 x KSTR) chunk buffers -> QK weights

    const int rt   = blockIdx.x;
    const int g    = blockIdx.y;
    const int b    = blockIdx.z;
    const int tid  = threadIdx.x;
    const int w    = tid >> 5;
    const int lane = tid & 31;
    const int r0   = rt * RT;

    const float* Qg = g_Qbuf[par][g] + (size_t)b * N_ * D_;
    const float* Kg = g_Kbuf[par][g] + (size_t)b * N_ * D_;
    const float* xsrc = from_x ? x + (((size_t)b * T_ + t) * N_) * D_
                               : g_Xbuf[par] + (size_t)b * N_ * D_;

    // ---- load Q tile ----
    for (int idx = tid; idx < RT * 64; idx += 256) {
        int r = idx >> 6, d = idx & 63;
        int qr = r0 + r;
        Qs[r * QSTR + d] = (qr < N_) ? Qg[(size_t)qr * D_ + d] : 0.0f;
    }

    float4 ld[4];

    // ---- Phase 1: S = Q K^T / 8 (double-buffered 64-key chunks) ----
#pragma unroll
    for (int i = 0; i < 4; i++) {
        int idx = tid + 256 * i;
        int key = idx >> 4, d4 = idx & 15;
        float4 v = make_float4(0.f, 0.f, 0.f, 0.f);
        if (key < N_) v = *(const float4*)(Kg + (size_t)key * D_ + 4 * d4);
        ld[i] = v;
    }
#pragma unroll
    for (int i = 0; i < 4; i++) {
        int idx = tid + 256 * i;
        int bs = (idx >> 4) * KSTR + 4 * (idx & 15);
        CH[bs] = ld[i].x; CH[bs + 1] = ld[i].y; CH[bs + 2] = ld[i].z; CH[bs + 3] = ld[i].w;
    }
    __syncthreads();

    for (int kc = 0; kc < 6; kc++) {
        float* cur = CH + (kc & 1) * CH_ONE;
        float* nxt = CH + ((kc + 1) & 1) * CH_ONE;
        if (kc < 5) {
            const int kb1 = (kc + 1) * 64;
#pragma unroll
            for (int i = 0; i < 4; i++) {
                int idx = tid + 256 * i;
                int key = idx >> 4, d4 = idx & 15;
                int gk = kb1 + key;
                float4 v = make_float4(0.f, 0.f, 0.f, 0.f);
                if (gk < N_) v = *(const float4*)(Kg + (size_t)gk * D_ + 4 * d4);
                ld[i] = v;
            }
        }
        ull acc[5][2] = {};
#pragma unroll
        for (int k = 0; k < 64; k += 4) {
            ulonglong2 q[5];
#pragma unroll
            for (int m = 0; m < 5; m++)
                q[m] = *(const ulonglong2*)&Qs[(w + 8 * m) * QSTR + k];
#pragma unroll
            for (int j = 0; j < 2; j++) {
                const int co = (lane + 32 * j) * KSTR;
                ull k0 = *(const ull*)&cur[co + k];
                ull k1 = *(const ull*)&cur[co + k + 2];
#pragma unroll
                for (int m = 0; m < 5; m++) {
                    ffma2(acc[m][j], q[m].x, k0);
                    ffma2(acc[m][j], q[m].y, k1);
                }
            }
        }
        const int kb = kc * 64;
#pragma unroll
        for (int j = 0; j < 2; j++) {
            int c = kb + lane + 32 * j;
#pragma unroll
            for (int m = 0; m < 5; m++)
                S[(w + 8 * m) * NPADS + c] = f2sum(acc[m][j]) * 0.125f;
        }
        if (kc < 5) {
#pragma unroll
            for (int i = 0; i < 4; i++) {
                int idx = tid + 256 * i;
                int bs = (idx >> 4) * KSTR + 4 * (idx & 15);
                nxt[bs] = ld[i].x; nxt[bs + 1] = ld[i].y;
                nxt[bs + 2] = ld[i].z; nxt[bs + 3] = ld[i].w;
            }
            __syncthreads();
        }
    }
    __syncwarp();

    // ---- Softmax (rows w+8i) + attn write ----
    const size_t attn_base = (g == 0 ? OFF_AI : OFF_AH);
    for (int rr = w; rr < RT; rr += 8) {
        int qr = r0 + rr;
        if (qr < N_) {
            float mx = -1e30f;
            for (int i = lane; i < N_; i += 32) mx = fmaxf(mx, S[rr * NPADS + i]);
#pragma unroll
            for (int o = 16; o; o >>= 1) mx = fmaxf(mx, __shfl_xor_sync(0xffffffffu, mx, o));
            float ss = 0.0f;
            for (int i = lane; i < NPADS; i += 32) {
                if (i < N_) {
                    float e = fexp(S[rr * NPADS + i] - mx);
                    S[rr * NPADS + i] = e;
                    ss += e;
                } else S[rr * NPADS + i] = 0.0f;
            }
#pragma unroll
            for (int o = 16; o; o >>= 1) ss += __shfl_xor_sync(0xffffffffu, ss, o);
            float inv = 1.0f / ss;
            float* arow = outf + attn_base +
                ((((size_t)b * T_ + t) * L_ + l) * N_ + qr) * (size_t)N_;
            for (int i = lane; i < N_; i += 32) {
                float p = S[rr * NPADS + i] * inv;
                S[rr * NPADS + i] = p;
                arow[i] = p;
            }
        } else {
            for (int i = lane; i < NPADS; i += 32) S[rr * NPADS + i] = 0.0f;
        }
    }

    // ---- Phase 2: PX = P @ x (x transposed chunks, double-buffered) ----
#pragma unroll
    for (int i = 0; i < 4; i++) {
        int idx = tid + 256 * i;
        int d4 = idx >> 6, key = idx & 63;
        float4 v = make_float4(0.f, 0.f, 0.f, 0.f);
        if (key < N_) v = *(const float4*)(xsrc + (size_t)key * D_ + 4 * d4);
        ld[i] = v;
    }
    __syncthreads();
#pragma unroll
    for (int i = 0; i < 4; i++) {
        int idx = tid + 256 * i;
        int d4 = idx >> 6, key = idx & 63;
        CH[(4 * d4)     * KSTR + key] = ld[i].x;
        CH[(4 * d4 + 1) * KSTR + key] = ld[i].y;
        CH[(4 * d4 + 2) * KSTR + key] = ld[i].z;
        CH[(4 * d4 + 3) * KSTR + key] = ld[i].w;
    }
    __syncthreads();

    ull acc2[5][2] = {};
    for (int kc = 0; kc < 6; kc++) {
        float* cur = CH + (kc & 1) * CH_ONE;
        float* nxt = CH + ((kc + 1) & 1) * CH_ONE;
        if (kc < 5) {
            const int kb1 = (kc + 1) * 64;
#pragma unroll
            for (int i = 0; i < 4; i++) {
                int idx = tid + 256 * i;
                int d4 = idx >> 6, key = idx & 63;
                int gk = kb1 + key;
                float4 v = make_float4(0.f, 0.f, 0.f, 0.f);
                if (gk < N_) v = *(const float4*)(xsrc + (size_t)gk * D_ + 4 * d4);
                ld[i] = v;
            }
        }
        const int kb = kc * 64;
#pragma unroll
        for (int kk = 0; kk < 64; kk += 4) {
            ulonglong2 p[5];
#pragma unroll
            for (int m = 0; m < 5; m++)
                p[m] = *(const ulonglong2*)&S[(w + 8 * m) * NPADS + kb + kk];
#pragma unroll
            for (int j = 0; j < 2; j++) {
                const int co = (lane + 32 * j) * KSTR;
                ull x0 = *(const ull*)&cur[co + kk];
                ull x1 = *(const ull*)&cur[co + kk + 2];
#pragma unroll
                for (int m = 0; m < 5; m++) {
                    ffma2(acc2[m][j], p[m].x, x0);
                    ffma2(acc2[m][j], p[m].y, x1);
                }
            }
        }
        if (kc < 5) {
#pragma unroll
            for (int i = 0; i < 4; i++) {
                int idx = tid + 256 * i;
                int d4 = idx >> 6, key = idx & 63;
                nxt[(4 * d4)     * KSTR + key] = ld[i].x;
                nxt[(4 * d4 + 1) * KSTR + key] = ld[i].y;
                nxt[(4 * d4 + 2) * KSTR + key] = ld[i].z;
                nxt[(4 * d4 + 3) * KSTR + key] = ld[i].w;
            }
            __syncthreads();
        }
    }
    // PX -> Qs (own rows)
#pragma unroll
    for (int m = 0; m < 5; m++)
#pragma unroll
        for (int j = 0; j < 2; j++)
            Qs[(w + 8 * m) * QSTR + lane + 32 * j] = f2sum(acc2[m][j]);
    __syncthreads();   // all P reads done before Wt overwrites S

    // ---- Phase 3: O = PX @ Wv + bias -> g_O ----
    {
        const float* W    = (g ? Wv_h : Wv_i) + (size_t)l * D_ * G_;
        const float* bias = (g ? b_h : b_i) + (size_t)l * G_;
        float* Wt = S;                     // 192 x KSTR = 12672 <= 15360
        for (int idx = tid; idx < 64 * G_; idx += 256) {
            int d = idx / G_, c = idx % G_;
            Wt[c * KSTR + d] = __ldg(&W[d * G_ + c]);
        }
        __syncthreads();

        float* Og = g_O[g] + (size_t)b * N_ * G_;
#pragma unroll
        for (int jg = 0; jg < 3; jg++) {
            ull acc3[5][2] = {};
#pragma unroll
            for (int d = 0; d < 64; d += 4) {
                ulonglong2 px[5];
#pragma unroll
                for (int m = 0; m < 5; m++)
                    px[m] = *(const ulonglong2*)&Qs[(w + 8 * m) * QSTR + d];
#pragma unroll
                for (int j = 0; j < 2; j++) {
                    const int c = jg * 64 + lane + 32 * j;
                    ull w0 = *(const ull*)&Wt[c * KSTR + d];
                    ull w1 = *(const ull*)&Wt[c * KSTR + d + 2];
#pragma unroll
                    for (int m = 0; m < 5; m++) {
                        ffma2(acc3[m][j], px[m].x, w0);
                        ffma2(acc3[m][j], px[m].y, w1);
                    }
                }
            }
#pragma unroll
            for (int m = 0; m < 5; m++) {
                int qr = r0 + w + 8 * m;
                if (qr < N_) {
#pragma unroll
                    for (int j = 0; j < 2; j++) {
                        int col = jg * 64 + lane + 32 * j;
                        Og[(size_t)qr * G_ + col] = f2sum(acc3[m][j]) + __ldg(&bias[col]);
                    }
                }
            }
        }
    }

    // ---- Last-arriver election ----
    __shared__ unsigned s_old;
    __threadfence();
    __syncthreads();
    if (tid == 0)
        s_old = atomicAdd(&g_flag[(s * 16 + b) * 9 + rt], 1u);
    __syncthreads();
    if (s_old == 0) return;    // first arriver exits; partner does the gate

    // ================= GATE + LN (both gats' O now in L2) ==================
    const float* O0 = g_O[0] + (size_t)b * N_ * G_;
    const float* O1 = g_O[1] + (size_t)b * N_ * G_;
    for (int rr = w; rr < RT; rr += 8) {
        int qr = r0 + rr;
        float o0 = 0.0f, o1 = 0.0f;
        float* hid = 0;
        if (qr < N_) {
            const float* oi = O0 + (size_t)qr * G_;
            const float* oh = O1 + (size_t)qr * G_;
            hid = outf + OFF_HID + (((size_t)b * L_ + l) * N_ + qr) * D_;
            int d0 = lane, d1 = lane + 32;
            float h0 = hid[d0], h1 = hid[d1];
            float rg0 = 1.0f / (1.0f + expf(-(oi[d0]       + oh[d0])));
            float ig0 = 1.0f / (1.0f + expf(-(oi[64 + d0]  + oh[64 + d0])));
            float ng0 = tanhf(oi[128 + d0] + rg0 * oh[128 + d0]);
            o0 = ng0 + ig0 * (h0 - ng0);
            float rg1 = 1.0f / (1.0f + expf(-(oi[d1]       + oh[d1])));
            float ig1 = 1.0f / (1.0f + expf(-(oi[64 + d1]  + oh[64 + d1])));
            float ng1 = tanhf(oi[128 + d1] + rg1 * oh[128 + d1]);
            o1 = ng1 + ig1 * (h1 - ng1);
        }
        float su = o0 + o1, qu = o0 * o0 + o1 * o1;
#pragma unroll
        for (int off = 16; off; off >>= 1) {
            su += __shfl_xor_sync(0xffffffffu, su, off);
            qu += __shfl_xor_sync(0xffffffffu, qu, off);
        }
        if (qr < N_) {
            float mu  = su * (1.0f / 64.0f);
            float var = qu * (1.0f / 64.0f) - mu * mu;
            float rs  = rsqrtf(var + 1e-5f);
            int d0 = lane, d1 = lane + 32;
            float y0 = (o0 - mu) * rs * __ldg(&ln_g[l * D_ + d0]) + __ldg(&ln_b[l * D_ + d0]);
            float y1 = (o1 - mu) * rs * __ldg(&ln_g[l * D_ + d1]) + __ldg(&ln_b[l * D_ + d1]);
            hid[d0] = y0; hid[d1] = y1;
            float* gx = g_Xbuf[par ^ 1] + ((size_t)b * N_ + qr) * D_;
            gx[d0] = y0; gx[d1] = y1;
            if (l == L_ - 1) {
                float* po = outf + OFF_OUT + (((size_t)b * T_ + t) * N_ + qr) * D_;
                po[d0] = y0; po[d1] = y1;
            }
            Qs[rr * QSTR + d0] = y0; Qs[rr * QSTR + d1] = y1;
        } else {
            Qs[rr * QSTR + lane] = 0.0f; Qs[rr * QSTR + lane + 32] = 0.0f;
        }
    }

    // ---- Next-stage Q/K for BOTH gats (this CTA's 40 rows) ----
    if (do_qk) {
        __syncthreads();
        if (l_next == 0) {
            const float* xn = x + (((size_t)b * T_ + (t + 1)) * N_) * D_;
            for (int idx = tid; idx < RT * 64; idx += 256) {
                int r = idx >> 6, d = idx & 63;
                int qr = r0 + r;
                Qs[r * QSTR + d] = (qr < N_) ? __ldg(&xn[(size_t)qr * D_ + d]) : 0.0f;
            }
            __syncthreads();
        }
#pragma unroll
        for (int gg = 0; gg < 2; gg++) {
            __syncthreads();   // CH free (prev pass reads done)
            const float* Wq = (gg ? Wq_h : Wq_i) + (size_t)l_next * D_ * D_;
            const float* Wk = (gg ? Wk_h : Wk_i) + (size_t)l_next * D_ * D_;
            for (int idx = tid; idx < 2 * 4096; idx += 256) {
                int mt = idx >> 12, r = (idx >> 6) & 63, c = idx & 63;
                const float* Wm = mt ? Wk : Wq;
                CH[mt * CH_ONE + c * KSTR + r] = __ldg(&Wm[r * 64 + c]);
            }
            __syncthreads();

            const int mat = w & 1, wr = w >> 1;
            const float* Wt2 = CH + mat * CH_ONE;
            ull aa[10][2] = {};
#pragma unroll
            for (int d = 0; d < 64; d += 4) {
                ull w00 = *(const ull*)&Wt2[lane * KSTR + d];
                ull w01 = *(const ull*)&Wt2[lane * KSTR + d + 2];
                ull w10 = *(const ull*)&Wt2[(lane + 32) * KSTR + d];
                ull w11 = *(const ull*)&Wt2[(lane + 32) * KSTR + d + 2];
#pragma unroll
                for (int m = 0; m < 10; m++) {
                    ulonglong2 y4 = *(const ulonglong2*)&Qs[(wr + 4 * m) * QSTR + d];
                    ffma2(aa[m][0], y4.x, w00);
                    ffma2(aa[m][0], y4.y, w01);
                    ffma2(aa[m][1], y4.x, w10);
                    ffma2(aa[m][1], y4.y, w11);
                }
            }
            float* Dd = (mat ? g_Kbuf[par ^ 1][gg] : g_Qbuf[par ^ 1][gg])
                        + (size_t)b * N_ * D_;
#pragma unroll
            for (int m = 0; m < 10; m++) {
                int qr = r0 + wr + 4 * m;
                if (qr < N_) {
                    Dd[(size_t)qr * D_ + lane]      = f2sum(aa[m][0]);
                    Dd[(size_t)qr * D_ + lane + 32] = f2sum(aa[m][1]);
                }
            }
        }
    }
}

// ---------------------------------------------------------------------------
extern "C" void kernel_launch(void* const* d_in, const int* in_sizes, int n_in,
                              void* d_out, int out_size) {
    const float* x    = (const float*)d_in[0];
    const float* Wq_i = (const float*)d_in[1];
    const float* Wk_i = (const float*)d_in[2];
    const float* Wv_i = (const float*)d_in[3];
    const float* b_i  = (const float*)d_in[4];
    const float* Wq_h = (const float*)d_in[5];
    const float* Wk_h = (const float*)d_in[6];
    const float* Wv_h = (const float*)d_in[7];
    const float* b_h  = (const float*)d_in[8];
    const float* ln_g = (const float*)d_in[9];
    const float* ln_b = (const float*)d_in[10];
    float* outf = (float*)d_out;

    const int k1_smem = K1_SMEM_FLOATS * (int)sizeof(float);  // 106,112 B
    cudaFuncSetAttribute(attn_gate_kernel, cudaFuncAttributeMaxDynamicSharedMemorySize, k1_smem);

    init_kernel<<<(int)((SZ_HID + 255) / 256), 256>>>(outf);
    qk_prologue<<<dim3(82, 4), 256>>>(x, Wq_i, Wk_i, Wq_h, Wk_h);

    dim3 grid(NTILES, 2, 16);
    for (int s = 0; s < T_ * L_; s++) {
        int t = s >> 1, l = s & 1;
        attn_gate_kernel<<<grid, 256, k1_smem>>>(
            s, t, l, (l == 0) ? 1 : 0, (s < T_ * L_ - 1) ? 1 : 0, l ^ 1, s & 1,
            x, Wq_i, Wk_i, Wv_i, b_i, Wq_h, Wk_h, Wv_h, b_h, ln_g, ln_b, outf);
    }
}

// round 17
// speedup vs baseline: 1.2165x; 1.2165x over previous
#include <cuda_runtime.h>
#include <cuda_bf16.h>
#include <math.h>

// Problem constants
#define B_  16
#define T_  12
#define N_  325
#define D_  64
#define L_  2
#define G_  192
#define BN  (B_ * N_)          // 5200

// d_out layout (floats): output, hidden, attn_input, attn_hidden
#define SZ_OUT ((size_t)B_ * T_ * N_ * D_)
#define SZ_HID ((size_t)B_ * L_ * N_ * D_)
#define SZ_A   ((size_t)B_ * T_ * L_ * N_ * N_)
#define OFF_OUT 0
#define OFF_HID (SZ_OUT)
#define OFF_AI  (SZ_OUT + SZ_HID)
#define OFF_AH  (SZ_OUT + SZ_HID + SZ_A)

// Scratch, parity double-buffered (stage s reads [s&1], writes [(s+1)&1])
__device__ float g_Xbuf[2][BN * D_];
__device__ float g_Qbuf[2][2][BN * D_];   // [parity][gat]
__device__ float g_Kbuf[2][2][BN * D_];

typedef unsigned long long ull;

__device__ __forceinline__ void ffma2(ull& d, ull a, ull b) {
    asm volatile("fma.rn.f32x2 %0, %1, %2, %0;" : "+l"(d) : "l"(a), "l"(b));
}
__device__ __forceinline__ float f2sum(ull v) {
    float lo, hi;
    asm("mov.b64 {%0, %1}, %2;" : "=f"(lo), "=f"(hi) : "l"(v));
    return lo + hi;
}
// FMA-pipe exp (x <= 0 here), ~1e-7 rel err.
__device__ __forceinline__ float fexp(float x) {
    float t = fmaxf(x * 1.4426950408889634f, -126.0f);
    float fi = floorf(t);
    float f = t - fi;
    float p =             1.535336188319500e-4f;
    p = fmaf(p, f, 1.339887440266574e-3f);
    p = fmaf(p, f, 9.618437357674640e-3f);
    p = fmaf(p, f, 5.550332471162809e-2f);
    p = fmaf(p, f, 2.402264791363012e-1f);
    p = fmaf(p, f, 6.931472028550421e-1f);
    p = fmaf(p, f, 1.0f);
    return p * __int_as_float(((int)fi + 127) << 23);
}

// ---------------------------------------------------------------------------
__global__ void zero_hidden_kernel(float* __restrict__ outf) {
    size_t i = (size_t)blockIdx.x * blockDim.x + threadIdx.x;
    if (i < SZ_HID) outf[OFF_HID + i] = 0.0f;
}

// ---------------------------------------------------------------------------
// Prologue: Q/K for stage (t=0,l=0) from x[:,0] -> parity 0. grid (82,4), 256.
// ---------------------------------------------------------------------------
__global__ void qk_prologue(const float* __restrict__ x,
                            const float* __restrict__ Wq_i, const float* __restrict__ Wk_i,
                            const float* __restrict__ Wq_h, const float* __restrict__ Wk_h) {
    __shared__ float Xs[64 * 68];
    __shared__ float Wt[64 * 66];
    const int rb = blockIdx.x, cb = blockIdx.y, tid = threadIdx.x;

    for (int idx = tid; idx < 64 * 64; idx += 256) {
        int r = idx >> 6, k = idx & 63;
        int row = rb * 64 + r;
        float v = 0.0f;
        if (row < BN) {
            int bb = row / N_, n = row - bb * N_;
            v = x[(((size_t)bb * T_) * N_ + n) * D_ + k];
        }
        Xs[r * 68 + k] = v;
    }
    const int g = cb >> 1, isK = cb & 1;
    const float* W = (g ? (isK ? Wk_h : Wq_h) : (isK ? Wk_i : Wq_i));
    for (int idx = tid; idx < 64 * 64; idx += 256) {
        int k = idx >> 6, c = idx & 63;
        Wt[c * 66 + k] = W[k * 64 + c];
    }
    __syncthreads();

    const int ty = tid >> 4, tx = tid & 15;
    ull acc[4][4] = {};
#pragma unroll
    for (int k = 0; k < 64; k += 4) {
        ulonglong2 xv[4];
#pragma unroll
        for (int m = 0; m < 4; m++)
            xv[m] = *(const ulonglong2*)&Xs[(ty + 16 * m) * 68 + k];
#pragma unroll
        for (int j = 0; j < 4; j++) {
            const int c = tx + 16 * j;
            ull w0 = *(const ull*)&Wt[c * 66 + k];
            ull w1 = *(const ull*)&Wt[c * 66 + k + 2];
#pragma unroll
            for (int m = 0; m < 4; m++) {
                ffma2(acc[m][j], xv[m].x, w0);
                ffma2(acc[m][j], xv[m].y, w1);
            }
        }
    }
    float* dst = isK ? g_Kbuf[0][g] : g_Qbuf[0][g];
#pragma unroll
    for (int m = 0; m < 4; m++) {
        int row = rb * 64 + ty + 16 * m;
        if (row < BN) {
#pragma unroll
            for (int j = 0; j < 4; j++)
                dst[(size_t)row * 64 + tx + 16 * j] = f2sum(acc[m][j]);
        }
    }
}

// ---------------------------------------------------------------------------
// MEGA kernel (R6 skeleton + double-buffered chunks + transposed-x phase 2).
// One launch per stage. grid (9, 16), block 512.
// Warps 0-7: input-gat, warps 8-15: hidden-gat. Warp wl owns rows wl+8m, m<5.
// ---------------------------------------------------------------------------
#define RT      40
#define NTILES  9
#define NPADS   384
#define QSTR    68
#define KSTR    66
#define CH_ONE  (64 * KSTR)          // 4224
#define QS_SZ   (RT * QSTR)          // 2720
#define S_SZ    (RT * NPADS)         // 15360
#define CH_SZ   (2 * CH_ONE)         // 8448 (double buffer; same as R6 footprint)
#define HALF_SZ (QS_SZ + S_SZ + CH_SZ)   // 26528
#define SMEM_FLOATS (2 * HALF_SZ)        // 53056 -> 212,224 B

__global__ __launch_bounds__(512)
void mega_kernel(int t, int l, int from_x, int do_qk, int l_next, int par,
                 const float* __restrict__ x,
                 const float* __restrict__ Wq_i, const float* __restrict__ Wk_i,
                 const float* __restrict__ Wv_i, const float* __restrict__ b_i,
                 const float* __restrict__ Wq_h, const float* __restrict__ Wk_h,
                 const float* __restrict__ Wv_h, const float* __restrict__ b_h,
                 const float* __restrict__ ln_g, const float* __restrict__ ln_b,
                 float* __restrict__ outf) {
    extern __shared__ float sm[];

    const int rt    = blockIdx.x;
    const int b     = blockIdx.y;
    const int tid   = threadIdx.x;
    const int half  = tid >> 8;          // gat index
    const int tid_h = tid & 255;
    const int wl    = tid_h >> 5;        // warp within half (0..7)
    const int wfull = tid >> 5;
    const int lane  = tid & 31;
    const int r0    = rt * RT;

    float* base = sm + half * HALF_SZ;
    float* Qs = base;                    // Q -> PX
    float* S  = base + QS_SZ;            // scores/P -> weight staging
    float* CH = base + QS_SZ + S_SZ;     // chunk double buffer -> O staging
    float* CH0 = sm + QS_SZ + S_SZ;
    float* CH1 = sm + HALF_SZ + QS_SZ + S_SZ;
    float* Ys  = sm;                     // shared y / x_{t+1} tile (half-0 Qs)

    const float* Qg = g_Qbuf[par][half] + (size_t)b * N_ * D_;
    const float* Kg = g_Kbuf[par][half] + (size_t)b * N_ * D_;
    const float* xsrc = from_x ? x + (((size_t)b * T_ + t) * N_) * D_
                               : g_Xbuf[par] + (size_t)b * N_ * D_;

    // ---- load Q tile ----
    for (int idx = tid_h; idx < RT * 64; idx += 256) {
        int r = idx >> 6, d = idx & 63;
        int qr = r0 + r;
        Qs[r * QSTR + d] = (qr < N_) ? Qg[(size_t)qr * D_ + d] : 0.0f;
    }

    float4 ld[4];

    // ---- Phase 1: S = Q K^T / 8 (double-buffered 64-key chunks) ----
#pragma unroll
    for (int i = 0; i < 4; i++) {
        int idx = tid_h + 256 * i;
        int key = idx >> 4, d4 = idx & 15;
        float4 v = make_float4(0.f, 0.f, 0.f, 0.f);
        if (key < N_) v = *(const float4*)(Kg + (size_t)key * D_ + 4 * d4);
        ld[i] = v;
    }
    __syncthreads();
#pragma unroll
    for (int i = 0; i < 4; i++) {
        int idx = tid_h + 256 * i;
        int bs = (idx >> 4) * KSTR + 4 * (idx & 15);
        CH[bs] = ld[i].x; CH[bs + 1] = ld[i].y; CH[bs + 2] = ld[i].z; CH[bs + 3] = ld[i].w;
    }
    __syncthreads();

    for (int kc = 0; kc < 6; kc++) {
        float* cur = CH + (kc & 1) * CH_ONE;
        float* nxt = CH + ((kc + 1) & 1) * CH_ONE;
        if (kc < 5) {
            const int kb1 = (kc + 1) * 64;
#pragma unroll
            for (int i = 0; i < 4; i++) {
                int idx = tid_h + 256 * i;
                int key = idx >> 4, d4 = idx & 15;
                int gk = kb1 + key;
                float4 v = make_float4(0.f, 0.f, 0.f, 0.f);
                if (gk < N_) v = *(const float4*)(Kg + (size_t)gk * D_ + 4 * d4);
                ld[i] = v;
            }
        }
        ull acc[5][2] = {};
#pragma unroll
        for (int k = 0; k < 64; k += 4) {
            ulonglong2 q[5];
#pragma unroll
            for (int m = 0; m < 5; m++)
                q[m] = *(const ulonglong2*)&Qs[(wl + 8 * m) * QSTR + k];
#pragma unroll
            for (int j = 0; j < 2; j++) {
                const int co = (lane + 32 * j) * KSTR;
                ull k0 = *(const ull*)&cur[co + k];
                ull k1 = *(const ull*)&cur[co + k + 2];
#pragma unroll
                for (int m = 0; m < 5; m++) {
                    ffma2(acc[m][j], q[m].x, k0);
                    ffma2(acc[m][j], q[m].y, k1);
                }
            }
        }
        const int kb = kc * 64;
#pragma unroll
        for (int j = 0; j < 2; j++) {
            int c = kb + lane + 32 * j;
#pragma unroll
            for (int m = 0; m < 5; m++)
                S[(wl + 8 * m) * NPADS + c] = f2sum(acc[m][j]) * 0.125f;
        }
        if (kc < 5) {
#pragma unroll
            for (int i = 0; i < 4; i++) {
                int idx = tid_h + 256 * i;
                int bs = (idx >> 4) * KSTR + 4 * (idx & 15);
                nxt[bs] = ld[i].x; nxt[bs + 1] = ld[i].y;
                nxt[bs + 2] = ld[i].z; nxt[bs + 3] = ld[i].w;
            }
            __syncthreads();
        }
    }
    __syncwarp();

    // ---- Softmax (warp-private rows wl+8m) + write attn to d_out ----
    const size_t attn_base = (half == 0 ? OFF_AI : OFF_AH);
#pragma unroll
    for (int m = 0; m < 5; m++) {
        int rr = wl + 8 * m;
        int qr = r0 + rr;
        if (qr < N_) {
            float mx = -1e30f;
            for (int i = lane; i < N_; i += 32) mx = fmaxf(mx, S[rr * NPADS + i]);
#pragma unroll
            for (int o = 16; o; o >>= 1) mx = fmaxf(mx, __shfl_xor_sync(0xffffffffu, mx, o));
            float ss = 0.0f;
            for (int i = lane; i < NPADS; i += 32) {
                if (i < N_) {
                    float e = fexp(S[rr * NPADS + i] - mx);
                    S[rr * NPADS + i] = e;
                    ss += e;
                } else S[rr * NPADS + i] = 0.0f;
            }
#pragma unroll
            for (int o = 16; o; o >>= 1) ss += __shfl_xor_sync(0xffffffffu, ss, o);
            float inv = 1.0f / ss;
            float* arow = outf + attn_base +
                ((((size_t)b * T_ + t) * L_ + l) * N_ + qr) * (size_t)N_;
            for (int i = lane; i < N_; i += 32) {
                float p = S[rr * NPADS + i] * inv;
                S[rr * NPADS + i] = p;
                arow[i] = p;
            }
        } else {
            for (int i = lane; i < NPADS; i += 32) S[rr * NPADS + i] = 0.0f;
        }
    }

    // ---- Phase 2: PX = P @ x (x TRANSPOSED chunks, double-buffered) ----
#pragma unroll
    for (int i = 0; i < 4; i++) {
        int idx = tid_h + 256 * i;
        int d4 = idx >> 6, key = idx & 63;
        float4 v = make_float4(0.f, 0.f, 0.f, 0.f);
        if (key < N_) v = *(const float4*)(xsrc + (size_t)key * D_ + 4 * d4);
        ld[i] = v;
    }
    __syncthreads();   // all warps done with phase-1 CH + softmax S writes
#pragma unroll
    for (int i = 0; i < 4; i++) {
        int idx = tid_h + 256 * i;
        int d4 = idx >> 6, key = idx & 63;
        CH[(4 * d4)     * KSTR + key] = ld[i].x;
        CH[(4 * d4 + 1) * KSTR + key] = ld[i].y;
        CH[(4 * d4 + 2) * KSTR + key] = ld[i].z;
        CH[(4 * d4 + 3) * KSTR + key] = ld[i].w;
    }
    __syncthreads();

    ull acc2[5][2] = {};
    for (int kc = 0; kc < 6; kc++) {
        float* cur = CH + (kc & 1) * CH_ONE;
        float* nxt = CH + ((kc + 1) & 1) * CH_ONE;
        if (kc < 5) {
            const int kb1 = (kc + 1) * 64;
#pragma unroll
            for (int i = 0; i < 4; i++) {
                int idx = tid_h + 256 * i;
                int d4 = idx >> 6, key = idx & 63;
                int gk = kb1 + key;
                float4 v = make_float4(0.f, 0.f, 0.f, 0.f);
                if (gk < N_) v = *(const float4*)(xsrc + (size_t)gk * D_ + 4 * d4);
                ld[i] = v;
            }
        }
        const int kb = kc * 64;
#pragma unroll
        for (int kk = 0; kk < 64; kk += 4) {
            ulonglong2 p[5];
#pragma unroll
            for (int m = 0; m < 5; m++)
                p[m] = *(const ulonglong2*)&S[(wl + 8 * m) * NPADS + kb + kk];
#pragma unroll
            for (int j = 0; j < 2; j++) {
                const int co = (lane + 32 * j) * KSTR;
                ull x0 = *(const ull*)&cur[co + kk];
                ull x1 = *(const ull*)&cur[co + kk + 2];
#pragma unroll
                for (int m = 0; m < 5; m++) {
                    ffma2(acc2[m][j], p[m].x, x0);
                    ffma2(acc2[m][j], p[m].y, x1);
                }
            }
        }
        if (kc < 5) {
#pragma unroll
            for (int i = 0; i < 4; i++) {
                int idx = tid_h + 256 * i;
                int d4 = idx >> 6, key = idx & 63;
                nxt[(4 * d4)     * KSTR + key] = ld[i].x;
                nxt[(4 * d4 + 1) * KSTR + key] = ld[i].y;
                nxt[(4 * d4 + 2) * KSTR + key] = ld[i].z;
                nxt[(4 * d4 + 3) * KSTR + key] = ld[i].w;
            }
            __syncthreads();
        }
    }
    // PX -> Qs (own rows; Q tile is dead)
#pragma unroll
    for (int m = 0; m < 5; m++)
#pragma unroll
        for (int j = 0; j < 2; j++)
            Qs[(wl + 8 * m) * QSTR + lane + 32 * j] = f2sum(acc2[m][j]);
    __syncthreads();   // all P reads done before Wt overwrites S

    // ---- Phase 3: O = PX @ Wv + bias -> CH (smem) ----
    {
        const float* W    = (half ? Wv_h : Wv_i) + (size_t)l * D_ * G_;
        const float* bias = (half ? b_h : b_i) + (size_t)l * G_;
        float* Wt = S;                       // [c][d] stride 66 (192*66 <= 15360)
        for (int idx = tid_h; idx < 64 * G_; idx += 256) {
            int d = idx / G_, c = idx % G_;
            Wt[c * KSTR + d] = W[d * G_ + c];
        }
        __syncthreads();

#pragma unroll
        for (int jg = 0; jg < 3; jg++) {
            ull acc3[5][2] = {};
#pragma unroll
            for (int d = 0; d < 64; d += 4) {
                ulonglong2 px[5];
#pragma unroll
                for (int m = 0; m < 5; m++)
                    px[m] = *(const ulonglong2*)&Qs[(wl + 8 * m) * QSTR + d];
#pragma unroll
                for (int j = 0; j < 2; j++) {
                    const int c = jg * 64 + lane + 32 * j;
                    ull w0 = *(const ull*)&Wt[c * KSTR + d];
                    ull w1 = *(const ull*)&Wt[c * KSTR + d + 2];
#pragma unroll
                    for (int m = 0; m < 5; m++) {
                        ffma2(acc3[m][j], px[m].x, w0);
                        ffma2(acc3[m][j], px[m].y, w1);
                    }
                }
            }
#pragma unroll
            for (int m = 0; m < 5; m++) {
#pragma unroll
                for (int j = 0; j < 2; j++) {
                    int c = jg * 64 + lane + 32 * j;
                    CH[(wl + 8 * m) * G_ + c] = f2sum(acc3[m][j]) + __ldg(&bias[c]);
                }
            }
        }
    }
    __syncthreads();

    // ---- Gate: GRU + LayerNorm (all 16 warps, warp-per-row) ----
    for (int rr = wfull; rr < RT; rr += 16) {
        int qr = r0 + rr;
        float o0 = 0.0f, o1 = 0.0f;
        float* hid = 0;
        if (qr < N_) {
            const float* oi = CH0 + rr * G_;
            const float* oh = CH1 + rr * G_;
            hid = outf + OFF_HID + (((size_t)b * L_ + l) * N_ + qr) * D_;
            int d0 = lane, d1 = lane + 32;
            float h0 = hid[d0], h1 = hid[d1];
            float rg0 = 1.0f / (1.0f + expf(-(oi[d0]       + oh[d0])));
            float ig0 = 1.0f / (1.0f + expf(-(oi[64 + d0]  + oh[64 + d0])));
            float ng0 = tanhf(oi[128 + d0] + rg0 * oh[128 + d0]);
            o0 = ng0 + ig0 * (h0 - ng0);
            float rg1 = 1.0f / (1.0f + expf(-(oi[d1]       + oh[d1])));
            float ig1 = 1.0f / (1.0f + expf(-(oi[64 + d1]  + oh[64 + d1])));
            float ng1 = tanhf(oi[128 + d1] + rg1 * oh[128 + d1]);
            o1 = ng1 + ig1 * (h1 - ng1);
        }
        float s = o0 + o1, q = o0 * o0 + o1 * o1;
#pragma unroll
        for (int off = 16; off; off >>= 1) {
            s += __shfl_xor_sync(0xffffffffu, s, off);
            q += __shfl_xor_sync(0xffffffffu, q, off);
        }
        if (qr < N_) {
            float mu  = s * (1.0f / 64.0f);
            float var = q * (1.0f / 64.0f) - mu * mu;
            float rs  = rsqrtf(var + 1e-5f);
            int d0 = lane, d1 = lane + 32;
            float y0 = (o0 - mu) * rs * __ldg(&ln_g[l * D_ + d0]) + __ldg(&ln_b[l * D_ + d0]);
            float y1 = (o1 - mu) * rs * __ldg(&ln_g[l * D_ + d1]) + __ldg(&ln_b[l * D_ + d1]);
            hid[d0] = y0; hid[d1] = y1;
            float* gx = g_Xbuf[par ^ 1] + ((size_t)b * N_ + qr) * D_;
            gx[d0] = y0; gx[d1] = y1;
            if (l == L_ - 1) {
                float* po = outf + OFF_OUT + (((size_t)b * T_ + t) * N_ + qr) * D_;
                po[d0] = y0; po[d1] = y1;
            }
            Ys[rr * QSTR + d0] = y0; Ys[rr * QSTR + d1] = y1;
        } else {
            Ys[rr * QSTR + lane] = 0.0f; Ys[rr * QSTR + lane + 32] = 0.0f;
        }
    }

    // ---- Epilogue: Q/K for next stage ----
    if (do_qk) {
        __syncthreads();
        if (l_next == 0) {
            const float* xn = x + (((size_t)b * T_ + (t + 1)) * N_) * D_;
            for (int idx = tid; idx < RT * 64; idx += 512) {
                int r = idx >> 6, d = idx & 63;
                int qr = r0 + r;
                Ys[r * QSTR + d] = (qr < N_) ? xn[(size_t)qr * D_ + d] : 0.0f;
            }
        }
        const float* Wq = (half ? Wq_h : Wq_i) + (size_t)l_next * D_ * D_;
        const float* Wk = (half ? Wk_h : Wk_i) + (size_t)l_next * D_ * D_;
        for (int idx = tid_h; idx < 64 * 64; idx += 256) {
            int d = idx >> 6, c = idx & 63;
            S[c * KSTR + d]        = Wq[d * 64 + c];
            S[4224 + c * KSTR + d] = Wk[d * 64 + c];
        }
        __syncthreads();

        ull aq[5][2] = {}, ak[5][2] = {};
#pragma unroll
        for (int d = 0; d < 64; d += 4) {
            ulonglong2 y4[5];
#pragma unroll
            for (int m = 0; m < 5; m++)
                y4[m] = *(const ulonglong2*)&Ys[(wl + 8 * m) * QSTR + d];
#pragma unroll
            for (int j = 0; j < 2; j++) {
                const int c = lane + 32 * j;
                ull wq0 = *(const ull*)&S[c * KSTR + d];
                ull wq1 = *(const ull*)&S[c * KSTR + d + 2];
                ull wk0 = *(const ull*)&S[4224 + c * KSTR + d];
                ull wk1 = *(const ull*)&S[4224 + c * KSTR + d + 2];
#pragma unroll
                for (int m = 0; m < 5; m++) {
                    ffma2(aq[m][j], y4[m].x, wq0);
                    ffma2(aq[m][j], y4[m].y, wq1);
                    ffma2(ak[m][j], y4[m].x, wk0);
                    ffma2(ak[m][j], y4[m].y, wk1);
                }
            }
        }
        float* Qd = g_Qbuf[par ^ 1][half] + (size_t)b * N_ * D_;
        float* Kd = g_Kbuf[par ^ 1][half] + (size_t)b * N_ * D_;
#pragma unroll
        for (int m = 0; m < 5; m++) {
            int qr = r0 + wl + 8 * m;
            if (qr < N_) {
#pragma unroll
                for (int j = 0; j < 2; j++) {
                    Qd[(size_t)qr * D_ + lane + 32 * j] = f2sum(aq[m][j]);
                    Kd[(size_t)qr * D_ + lane + 32 * j] = f2sum(ak[m][j]);
                }
            }
        }
    }
}

// ---------------------------------------------------------------------------
extern "C" void kernel_launch(void* const* d_in, const int* in_sizes, int n_in,
                              void* d_out, int out_size) {
    const float* x    = (const float*)d_in[0];
    const float* Wq_i = (const float*)d_in[1];
    const float* Wk_i = (const float*)d_in[2];
    const float* Wv_i = (const float*)d_in[3];
    const float* b_i  = (const float*)d_in[4];
    const float* Wq_h = (const float*)d_in[5];
    const float* Wk_h = (const float*)d_in[6];
    const float* Wv_h = (const float*)d_in[7];
    const float* b_h  = (const float*)d_in[8];
    const float* ln_g = (const float*)d_in[9];
    const float* ln_b = (const float*)d_in[10];
    float* outf = (float*)d_out;

    const int mega_smem = SMEM_FLOATS * (int)sizeof(float);   // 212,224 B
    cudaFuncSetAttribute(mega_kernel, cudaFuncAttributeMaxDynamicSharedMemorySize, mega_smem);

    zero_hidden_kernel<<<(int)((SZ_HID + 255) / 256), 256>>>(outf);
    qk_prologue<<<dim3(82, 4), 256>>>(x, Wq_i, Wk_i, Wq_h, Wk_h);

    dim3 mega_grid(NTILES, 16);
    for (int s = 0; s < T_ * L_; s++) {
        int t = s >> 1, l = s & 1;
        mega_kernel<<<mega_grid, 512, mega_smem>>>(
            t, l, (l == 0) ? 1 : 0, (s < T_ * L_ - 1) ? 1 : 0, l ^ 1, s & 1,
            x, Wq_i, Wk_i, Wv_i, b_i, Wq_h, Wk_h, Wv_h, b_h, ln_g, ln_b, outf);
    }
}